// round 13
// baseline (speedup 1.0000x reference)
#include <cuda_runtime.h>
#include <cuda_fp16.h>
#include <math.h>
#include <stdint.h>

// Problem dims
constexpr int BB = 8;
constexpr int SS = 1024;
constexpr int DD = 256;
constexpr int MTOT = BB * SS;          // 8192
constexpr int TC = 16;                 // chunk length
constexpr int CH = SS / TC;            // 64 chunks
constexpr int LDR = 260;               // padded smem row stride (256-col tiles)
constexpr int LDRH = 132;              // padded smem row stride (128-col tiles)

// Scratch (device globals — no cudaMalloc allowed)
__device__ float g_q[MTOT * DD];
__device__ float g_k[MTOT * DD];
__device__ float g_f[MTOT * DD];
__device__ float g_i[MTOT * DD];
__device__ float g_n[MTOT * DD];
__device__ float g_h[MTOT * DD];
__device__ float g_inv[MTOT + 64];
// chunkwise scan scratch
__device__ __half g_Csh[(size_t)BB * CH * DD * DD];  // 64 MB: C at chunk start (fp16)
__device__ float g_G[BB * CH * TC * DD];             // gate prefix products
__device__ float g_a[BB * CH * TC * DD];             // normalized input coeffs
__device__ float g_P[BB * CH * TC * TC];             // k_s . q_t per chunk

typedef unsigned long long ull;

// ---- f32x2 helpers ----
__device__ __forceinline__ ull pack2(float lo, float hi) {
    ull r; asm("mov.b64 %0, {%1, %2};" : "=l"(r) : "f"(lo), "f"(hi)); return r;
}
__device__ __forceinline__ ull fma2(ull a, ull b, ull c) {
    ull d; asm("fma.rn.f32x2 %0, %1, %2, %3;" : "=l"(d) : "l"(a), "l"(b), "l"(c)); return d;
}
__device__ __forceinline__ ull mul2(ull a, ull b) {
    ull d; asm("mul.rn.f32x2 %0, %1, %2;" : "=l"(d) : "l"(a), "l"(b)); return d;
}
__device__ __forceinline__ ull add2(ull a, ull b) {
    ull d; asm("add.rn.f32x2 %0, %1, %2;" : "=l"(d) : "l"(a), "l"(b)); return d;
}
__device__ __forceinline__ void unpack2(ull v, float& lo, float& hi) {
    asm("mov.b64 {%0, %1}, %2;" : "=f"(lo), "=f"(hi) : "l"(v));
}
__device__ __forceinline__ float hsum2(ull v) {
    float lo, hi; unpack2(v, lo, hi); return lo + hi;
}
__device__ __forceinline__ uint32_t f2_to_h2(float lo, float hi) {
    __half2 h = __floats2half2_rn(lo, hi);
    return *(uint32_t*)&h;
}

// ---- cp.async helpers ----
__device__ __forceinline__ void cp_async16(uint32_t saddr, const void* gptr) {
    asm volatile("cp.async.ca.shared.global [%0], [%1], 16;" :: "r"(saddr), "l"(gptr));
}
__device__ __forceinline__ void cp_commit() { asm volatile("cp.async.commit_group;"); }
template <int N>
__device__ __forceinline__ void cp_wait() {
    asm volatile("cp.async.wait_group %0;" :: "n"(N));
}

// ---------------------------------------------------------------------------
// Fused input GEMM: z selects (Wq,Wk,Wf,Wi); grid (2,64,4).
// NOTE: plain launch_bounds(256) — forcing 2 CTAs/SM caused register spills.
// ---------------------------------------------------------------------------
__global__ void __launch_bounds__(256) gemm4_kernel(
    const float* __restrict__ x,
    const float* __restrict__ W0, const float* __restrict__ b0,
    const float* __restrict__ W1, const float* __restrict__ b1,
    const float* __restrict__ W2, const float* __restrict__ b2,
    const float* __restrict__ W3, const float* __restrict__ b3,
    float* __restrict__ o0, float* __restrict__ o1,
    float* __restrict__ o2, float* __restrict__ o3)
{
    __shared__ float As[8][132];
    __shared__ float Bs[8][132];

    const int z = blockIdx.z;
    const float* W = (z == 0) ? W0 : (z == 1) ? W1 : (z == 2) ? W2 : W3;
    const float* bias = (z == 0) ? b0 : (z == 1) ? b1 : (z == 2) ? b2 : b3;
    float* out = (z == 0) ? o0 : (z == 1) ? o1 : (z == 2) ? o2 : o3;

    const int tid = threadIdx.x;
    const int m0 = blockIdx.y * 128;
    const int n0 = blockIdx.x * 128;
    const int lm = tid >> 1;
    const int lk = (tid & 1) << 2;
    const int tx = tid & 15;
    const int ty = tid >> 4;

    ull acc2[8][4] = {};

    float4 a4 = *(const float4*)(x + (size_t)(m0 + lm) * DD + lk);
    float4 w4 = *(const float4*)(W + (size_t)(n0 + lm) * DD + lk);

    for (int k0 = 0; k0 < DD; k0 += 8) {
        __syncthreads();
        As[lk + 0][lm] = a4.x; As[lk + 1][lm] = a4.y;
        As[lk + 2][lm] = a4.z; As[lk + 3][lm] = a4.w;
        Bs[lk + 0][lm] = w4.x; Bs[lk + 1][lm] = w4.y;
        Bs[lk + 2][lm] = w4.z; Bs[lk + 3][lm] = w4.w;
        __syncthreads();
        if (k0 + 8 < DD) {
            a4 = *(const float4*)(x + (size_t)(m0 + lm) * DD + k0 + 8 + lk);
            w4 = *(const float4*)(W + (size_t)(n0 + lm) * DD + k0 + 8 + lk);
        }
#pragma unroll
        for (int kk = 0; kk < 8; kk++) {
            float4 av0 = *(const float4*)&As[kk][ty * 8];
            float4 av1 = *(const float4*)&As[kk][ty * 8 + 4];
            float4 bv0 = *(const float4*)&Bs[kk][tx * 8];
            float4 bv1 = *(const float4*)&Bs[kk][tx * 8 + 4];
            ull b0p = pack2(bv0.x, bv0.y);
            ull b1p = pack2(bv0.z, bv0.w);
            ull b2p = pack2(bv1.x, bv1.y);
            ull b3p = pack2(bv1.z, bv1.w);
            float am[8] = {av0.x, av0.y, av0.z, av0.w, av1.x, av1.y, av1.z, av1.w};
#pragma unroll
            for (int i2 = 0; i2 < 8; i2++) {
                ull aa = pack2(am[i2], am[i2]);
                acc2[i2][0] = fma2(aa, b0p, acc2[i2][0]);
                acc2[i2][1] = fma2(aa, b1p, acc2[i2][1]);
                acc2[i2][2] = fma2(aa, b2p, acc2[i2][2]);
                acc2[i2][3] = fma2(aa, b3p, acc2[i2][3]);
            }
        }
    }

    float4 bb0 = *(const float4*)(bias + n0 + tx * 8);
    float4 bb1 = *(const float4*)(bias + n0 + tx * 8 + 4);
    float bb[8] = {bb0.x, bb0.y, bb0.z, bb0.w, bb1.x, bb1.y, bb1.z, bb1.w};
#pragma unroll
    for (int i2 = 0; i2 < 8; i2++) {
        float r[8];
        unpack2(acc2[i2][0], r[0], r[1]);
        unpack2(acc2[i2][1], r[2], r[3]);
        unpack2(acc2[i2][2], r[4], r[5]);
        unpack2(acc2[i2][3], r[6], r[7]);
        float4 q0, q1;
#pragma unroll
        for (int j2 = 0; j2 < 8; j2++) {
            float v = r[j2] + bb[j2];
            if (z == 2) v = 1.0f / (1.0f + expf(-v));
            else if (z == 3) v = expf(v);
            if (j2 < 4) (&q0.x)[j2] = v; else (&q1.x)[j2 - 4] = v;
        }
        float* dst = out + (size_t)(m0 + ty * 8 + i2) * DD + n0 + tx * 8;
        *(float4*)dst = q0;
        *(float4*)(dst + 4) = q1;
    }
}

// ---------------------------------------------------------------------------
// Output GEMM (plain launch bounds)
// ---------------------------------------------------------------------------
__global__ void __launch_bounds__(256) gemm_out_kernel(
    const float* __restrict__ A, const float* __restrict__ W,
    const float* __restrict__ bias, float* __restrict__ out)
{
    __shared__ float As[8][132];
    __shared__ float Bs[8][132];

    const int tid = threadIdx.x;
    const int m0 = blockIdx.y * 128;
    const int n0 = blockIdx.x * 128;
    const int lm = tid >> 1;
    const int lk = (tid & 1) << 2;
    const int tx = tid & 15;
    const int ty = tid >> 4;

    ull acc2[8][4] = {};

    float4 a4 = *(const float4*)(A + (size_t)(m0 + lm) * DD + lk);
    float4 w4 = *(const float4*)(W + (size_t)(n0 + lm) * DD + lk);

    for (int k0 = 0; k0 < DD; k0 += 8) {
        __syncthreads();
        As[lk + 0][lm] = a4.x; As[lk + 1][lm] = a4.y;
        As[lk + 2][lm] = a4.z; As[lk + 3][lm] = a4.w;
        Bs[lk + 0][lm] = w4.x; Bs[lk + 1][lm] = w4.y;
        Bs[lk + 2][lm] = w4.z; Bs[lk + 3][lm] = w4.w;
        __syncthreads();
        if (k0 + 8 < DD) {
            a4 = *(const float4*)(A + (size_t)(m0 + lm) * DD + k0 + 8 + lk);
            w4 = *(const float4*)(W + (size_t)(n0 + lm) * DD + k0 + 8 + lk);
        }
#pragma unroll
        for (int kk = 0; kk < 8; kk++) {
            float4 av0 = *(const float4*)&As[kk][ty * 8];
            float4 av1 = *(const float4*)&As[kk][ty * 8 + 4];
            float4 bv0 = *(const float4*)&Bs[kk][tx * 8];
            float4 bv1 = *(const float4*)&Bs[kk][tx * 8 + 4];
            ull b0p = pack2(bv0.x, bv0.y);
            ull b1p = pack2(bv0.z, bv0.w);
            ull b2p = pack2(bv1.x, bv1.y);
            ull b3p = pack2(bv1.z, bv1.w);
            float am[8] = {av0.x, av0.y, av0.z, av0.w, av1.x, av1.y, av1.z, av1.w};
#pragma unroll
            for (int i2 = 0; i2 < 8; i2++) {
                ull aa = pack2(am[i2], am[i2]);
                acc2[i2][0] = fma2(aa, b0p, acc2[i2][0]);
                acc2[i2][1] = fma2(aa, b1p, acc2[i2][1]);
                acc2[i2][2] = fma2(aa, b2p, acc2[i2][2]);
                acc2[i2][3] = fma2(aa, b3p, acc2[i2][3]);
            }
        }
    }

    float4 bb0 = *(const float4*)(bias + n0 + tx * 8);
    float4 bb1 = *(const float4*)(bias + n0 + tx * 8 + 4);
    float bb[8] = {bb0.x, bb0.y, bb0.z, bb0.w, bb1.x, bb1.y, bb1.z, bb1.w};
#pragma unroll
    for (int i2 = 0; i2 < 8; i2++) {
        float r[8];
        unpack2(acc2[i2][0], r[0], r[1]);
        unpack2(acc2[i2][1], r[2], r[3]);
        unpack2(acc2[i2][2], r[4], r[5]);
        unpack2(acc2[i2][3], r[6], r[7]);
        float4 q0, q1;
#pragma unroll
        for (int j2 = 0; j2 < 8; j2++) {
            float v = r[j2] + bb[j2];
            if (j2 < 4) (&q0.x)[j2] = v; else (&q1.x)[j2 - 4] = v;
        }
        float* dst = out + (size_t)(m0 + ty * 8 + i2) * DD + n0 + tx * 8;
        *(float4*)dst = q0;
        *(float4*)(dst + 4) = q1;
    }
}

// ---------------------------------------------------------------------------
// n-scan: 2048 chains
// ---------------------------------------------------------------------------
__global__ void nscan_kernel()
{
    const int cid = blockIdx.x * 32 + threadIdx.x;
    const int b = cid >> 8;
    const int j = cid & 255;
    const size_t base = (size_t)b * SS * DD + j;
    float n = 0.0f;
#pragma unroll 16
    for (int t = 0; t < SS; t++) {
        size_t o = base + (size_t)t * DD;
        n = fmaf(g_f[o], n, g_i[o] * g_k[o]);
        g_n[o] = n;
    }
}

// ---------------------------------------------------------------------------
// P1: per (b,chunk) — gates G/a, P = k.q^T, AND inv_den. grid = 512.
// ---------------------------------------------------------------------------
__global__ void __launch_bounds__(256) p1_kernel()
{
    __shared__ float sk[TC][LDR];
    __shared__ float sq[TC][DD];
    __shared__ float sn[TC][DD];

    const int bm = blockIdx.x;
    const int b = bm >> 6, m = bm & 63;
    const int tid = threadIdx.x;
    const size_t mb = (size_t)b * SS * DD;
    const int tt = m * TC;

#pragma unroll
    for (int v = 0; v < 4; v++) {
        int idx = tid + v * 256;
        int t = idx >> 6, gr = idx & 63;
        *(float4*)&sk[t][gr * 4] =
            *(const float4*)(g_k + mb + (size_t)(tt + t) * DD + gr * 4);
        *(float4*)&sq[t][gr * 4] =
            *(const float4*)(g_q + mb + (size_t)(tt + t) * DD + gr * 4);
        *(float4*)&sn[t][gr * 4] =
            *(const float4*)(g_n + mb + (size_t)(tt + t) * DD + gr * 4);
    }
    // gates: thread = channel i
    {
        const int i = tid;
        float g = 1.0f;
#pragma unroll
        for (int u = 0; u < TC; u++) {
            size_t o = mb + (size_t)(tt + u) * DD + i;
            float f = g_f[o], ii = g_i[o], vv = g_q[o];   // v == q
            g *= f;
            float av = __fdividef(ii * vv, g);
            g_G[(size_t)(bm * TC + u) * DD + i] = g;
            g_a[(size_t)(bm * TC + u) * DD + i] = av;
        }
    }
    __syncthreads();

    // P[t][j] = k_j . q_t
    {
        const int t = tid >> 4, j = tid & 15;
        ull acc0 = 0, acc1 = 0;
#pragma unroll 8
        for (int c = 0; c < DD; c += 4) {
            float4 k4 = *(const float4*)&sk[j][c];
            float4 q4 = *(const float4*)&sq[t][c];
            acc0 = fma2(pack2(k4.x, k4.y), pack2(q4.x, q4.y), acc0);
            acc1 = fma2(pack2(k4.z, k4.w), pack2(q4.z, q4.w), acc1);
        }
        g_P[(size_t)bm * TC * TC + t * TC + j] = hsum2(add2(acc0, acc1));
    }
    // inv_den: 16 threads, one per t
    if (tid < TC) {
        const int t = tid;
        ull a0 = 0, a1 = 0;
#pragma unroll 8
        for (int c = 0; c < DD; c += 4) {
            float4 n4 = *(const float4*)&sn[t][c];
            float4 q4 = *(const float4*)&sq[t][c];
            a0 = fma2(pack2(n4.x, n4.y), pack2(q4.x, q4.y), a0);
            a1 = fma2(pack2(n4.z, n4.w), pack2(q4.z, q4.w), a1);
        }
        float d = hsum2(add2(a0, a1));
        g_inv[b * SS + tt + t] = 1.0f / fmaxf(fabsf(d), 1.0f);
    }
}

// ---------------------------------------------------------------------------
// P2: serial chunk scan, C in registers, fp16 snapshots. COLUMN-SPLIT:
// grid = 256 CTAs: (b, 16-row group rg, column half ch). Each CTA owns
// 16 rows x 128 cols. Thread (rq=tid>>5 -> rows 2rq..2rq+1, cq=tid&31 ->
// cols 4cq..4cq+3 within half). Per chunk: snapshot fp16, recompute
// rank-16 update from k (smem, L2-hot) and a.
// ---------------------------------------------------------------------------
__global__ void __launch_bounds__(256) p2_kernel()
{
    __shared__ float sk[2][TC][LDRH];     // 16 rows x 128 cols (padded)
    __shared__ float sa[2][TC][16];
    __shared__ float sg15[2][16];

    const int ch = blockIdx.x & 1;        // column half
    const int rg = (blockIdx.x >> 1) & 15;
    const int b  = blockIdx.x >> 5;
    const int rowb = rg * 16;
    const int colb = ch * 128;
    const int tid = threadIdx.x;
    const int rq = tid >> 5;              // 0..7 -> rows 2rq, 2rq+1
    const int cq = tid & 31;              // cols colb + 4cq .. +3
    const size_t mb = (size_t)b * SS * DD;

    const uint32_t sk_u = (uint32_t)__cvta_generic_to_shared(&sk[0][0][0]);
    const uint32_t sa_u = (uint32_t)__cvta_generic_to_shared(&sa[0][0][0]);
    const uint32_t sg_u = (uint32_t)__cvta_generic_to_shared(&sg15[0][0]);

    auto fill = [&](int st, int mm) {
        const int tt = mm * TC;
        const int bm = b * CH + mm;
#pragma unroll
        for (int v = 0; v < 2; v++) {                 // k: 512 granules (16t x 32)
            int idx = tid + v * 256;
            int t = idx >> 5, gr = idx & 31;
            cp_async16(sk_u + (uint32_t)(((st * TC + t) * LDRH + gr * 4) * 4),
                       g_k + mb + (size_t)(tt + t) * DD + colb + gr * 4);
        }
        if (tid < 64) {
            int s = tid >> 2, p = tid & 3;
            cp_async16(sa_u + (uint32_t)(((st * TC + s) * 16 + p * 4) * 4),
                       g_a + (size_t)(bm * TC + s) * DD + rowb + p * 4);
        } else if (tid < 68) {
            int p = tid - 64;
            cp_async16(sg_u + (uint32_t)((st * 16 + p * 4) * 4),
                       g_G + (size_t)(bm * TC + 15) * DD + rowb + p * 4);
        }
    };

    ull Cp[2][2];                          // 2 rows x 4 cols (f32x2 pairs)
    Cp[0][0] = Cp[0][1] = Cp[1][0] = Cp[1][1] = 0ull;

    fill(0, 0); cp_commit();
    fill(1, 1); cp_commit();

    for (int m = 0; m < CH; m++) {
        const int st = m & 1;
        cp_wait<1>();
        __syncthreads();

        // snapshot C (fp16): 2 rows x 4 halfs = 8 B each (coalesced in cq)
        {
            const int bm = b * CH + m;
#pragma unroll
            for (int r = 0; r < 2; r++) {
                float l0, h0, l1, h1;
                unpack2(Cp[r][0], l0, h0);
                unpack2(Cp[r][1], l1, h1);
                uint2 u;
                u.x = f2_to_h2(l0, h0);
                u.y = f2_to_h2(l1, h1);
                __half* dst = g_Csh + ((size_t)bm * DD + rowb + rq * 2 + r) * DD
                              + colb + cq * 4;
                *(uint2*)dst = u;
            }
        }

        // update: C = g15 * (C + sum_s a[s][rows] * k[s][cols])
        {
            ull acc[2][2];
            acc[0][0] = acc[0][1] = acc[1][0] = acc[1][1] = 0ull;
#pragma unroll 8
            for (int s = 0; s < TC; s++) {
                float2 a2 = *(const float2*)&sa[st][s][rq * 2];
                float4 k4 = *(const float4*)&sk[st][s][cq * 4];
                ull kxy = pack2(k4.x, k4.y), kzw = pack2(k4.z, k4.w);
                ull a0 = pack2(a2.x, a2.x);
                ull a1 = pack2(a2.y, a2.y);
                acc[0][0] = fma2(a0, kxy, acc[0][0]);
                acc[0][1] = fma2(a0, kzw, acc[0][1]);
                acc[1][0] = fma2(a1, kxy, acc[1][0]);
                acc[1][1] = fma2(a1, kzw, acc[1][1]);
            }
            float2 g2v = *(const float2*)&sg15[st][rq * 2];
            ull g0 = pack2(g2v.x, g2v.x);
            ull g1 = pack2(g2v.y, g2v.y);
            Cp[0][0] = mul2(g0, add2(Cp[0][0], acc[0][0]));
            Cp[0][1] = mul2(g0, add2(Cp[0][1], acc[0][1]));
            Cp[1][0] = mul2(g1, add2(Cp[1][0], acc[1][0]));
            Cp[1][1] = mul2(g1, add2(Cp[1][1], acc[1][1]));
        }
        __syncthreads();

        if (m + 2 < CH) fill(st, m + 2);
        cp_commit();
    }
}

// ---------------------------------------------------------------------------
// P3: per (b,chunk,32-row group) — CQ = Cs.q^T + triangular combine.
// grid = 4096, 128 threads.
// ---------------------------------------------------------------------------
struct P3Smem {
    float q[TC][LDR];
    float Cs[32][LDR];
    float a[TC][32];
    float G[TC][32];
    float P[TC][TC];
    float inv[TC];
    float htile[TC][32];
};

__global__ void __launch_bounds__(128) p3_kernel()
{
    __shared__ P3Smem S;
    const int blk = blockIdx.x;
    const int bm = blk >> 3;
    const int rg = blk & 7;
    const int b = bm >> 6, m = bm & 63;
    const int tid = threadIdx.x;
    const int rowb = rg * 32;
    const size_t mb = (size_t)b * SS * DD;
    const int tt = m * TC;

#pragma unroll
    for (int v = 0; v < 8; v++) {
        int idx = tid + v * 128;
        int t = idx >> 6, gr = idx & 63;
        *(float4*)&S.q[t][gr * 4] =
            *(const float4*)(g_q + mb + (size_t)(tt + t) * DD + gr * 4);
    }
#pragma unroll
    for (int v = 0; v < 8; v++) {
        int idx = tid + v * 128;
        int r = idx >> 5, u = idx & 31;
        uint4 raw = *(const uint4*)(g_Csh + ((size_t)bm * DD + rowb + r) * DD + u * 8);
        const __half2* hp = (const __half2*)&raw;
        float2 f0 = __half22float2(hp[0]);
        float2 f1 = __half22float2(hp[1]);
        float2 f2 = __half22float2(hp[2]);
        float2 f3 = __half22float2(hp[3]);
        *(float4*)&S.Cs[r][u * 8]     = make_float4(f0.x, f0.y, f1.x, f1.y);
        *(float4*)&S.Cs[r][u * 8 + 4] = make_float4(f2.x, f2.y, f3.x, f3.y);
    }
#pragma unroll
    for (int v = 0; v < 4; v++) {
        int idx = tid + v * 128;
        int s = (idx & 127) >> 3, p = idx & 7;
        if (idx < 128)
            *(float4*)&S.a[s][p * 4] =
                *(const float4*)(g_a + (size_t)(bm * TC + s) * DD + rowb + p * 4);
        else if (idx < 256)
            *(float4*)&S.G[s][p * 4] =
                *(const float4*)(g_G + (size_t)(bm * TC + s) * DD + rowb + p * 4);
        else if (idx < 320) {
            int ii = idx - 256;
            int t2 = ii >> 2, p2 = ii & 3;
            *(float4*)&S.P[t2][p2 * 4] =
                *(const float4*)(g_P + (size_t)bm * 256 + t2 * 16 + p2 * 4);
        } else if (idx < 324) {
            int p3 = idx - 320;
            *(float4*)&S.inv[p3 * 4] =
                *(const float4*)(g_inv + b * SS + tt + p3 * 4);
        }
    }
    __syncthreads();

    const int r2 = tid & 15;
    const int nh = tid >> 4;
    const int rA = r2, rB = r2 + 16;
    const int tA = nh, tB = nh + 8;

    ull cAA0 = 0, cAA1 = 0, cAB0 = 0, cAB1 = 0;
    ull cBA0 = 0, cBA1 = 0, cBB0 = 0, cBB1 = 0;
    const float* CrA = &S.Cs[rA][0];
    const float* CrB = &S.Cs[rB][0];
    const float* q0 = &S.q[tA][0];
    const float* q1 = &S.q[tB][0];
#pragma unroll 8
    for (int c = 0; c < DD; c += 4) {
        float4 CA = *(const float4*)(CrA + c);
        float4 CB = *(const float4*)(CrB + c);
        float4 B0 = *(const float4*)(q0 + c);
        float4 B1 = *(const float4*)(q1 + c);
        ull Axy = pack2(CA.x, CA.y), Azw = pack2(CA.z, CA.w);
        ull Bxy = pack2(CB.x, CB.y), Bzw = pack2(CB.z, CB.w);
        ull q0xy = pack2(B0.x, B0.y), q0zw = pack2(B0.z, B0.w);
        ull q1xy = pack2(B1.x, B1.y), q1zw = pack2(B1.z, B1.w);
        cAA0 = fma2(Axy, q0xy, cAA0); cAA1 = fma2(Azw, q0zw, cAA1);
        cAB0 = fma2(Axy, q1xy, cAB0); cAB1 = fma2(Azw, q1zw, cAB1);
        cBA0 = fma2(Bxy, q0xy, cBA0); cBA1 = fma2(Bzw, q0zw, cBA1);
        cBB0 = fma2(Bxy, q1xy, cBB0); cBB1 = fma2(Bzw, q1zw, cBB1);
    }
    float CQ_AA = hsum2(add2(cAA0, cAA1));
    float CQ_AB = hsum2(add2(cAB0, cAB1));
    float CQ_BA = hsum2(add2(cBA0, cBA1));
    float CQ_BB = hsum2(add2(cBB0, cBB1));

    {
        float nAA = CQ_AA, nBA = CQ_BA;
#pragma unroll
        for (int s = 0; s < TC; s++)
            if (s <= tA) {
                float p = S.P[tA][s];
                nAA = fmaf(S.a[s][rA], p, nAA);
                nBA = fmaf(S.a[s][rB], p, nBA);
            }
        S.htile[tA][rA] = S.G[tA][rA] * nAA * S.inv[tA];
        S.htile[tA][rB] = S.G[tA][rB] * nBA * S.inv[tA];

        float nAB = CQ_AB, nBB = CQ_BB;
#pragma unroll
        for (int s = 0; s < TC; s++)
            if (s <= tB) {
                float p = S.P[tB][s];
                nAB = fmaf(S.a[s][rA], p, nAB);
                nBB = fmaf(S.a[s][rB], p, nBB);
            }
        S.htile[tB][rA] = S.G[tB][rA] * nAB * S.inv[tB];
        S.htile[tB][rB] = S.G[tB][rB] * nBB * S.inv[tB];
    }
    __syncthreads();

    {
        const int t = tid >> 3, seg = tid & 7;
        *(float4*)(g_h + mb + (size_t)(tt + t) * DD + rowb + seg * 4) =
            *(const float4*)&S.htile[t][seg * 4];
    }
}

// ---------------------------------------------------------------------------
// Launch
// ---------------------------------------------------------------------------
extern "C" void kernel_launch(void* const* d_in, const int* in_sizes, int n_in,
                              void* d_out, int out_size)
{
    const float* x   = (const float*)d_in[0];
    const float* Wq  = (const float*)d_in[1];
    const float* bq  = (const float*)d_in[2];
    const float* Wk  = (const float*)d_in[3];
    const float* bkk = (const float*)d_in[4];
    // d_in[5] = Wv, d_in[6] = bv — unused (reference uses W_q for v)
    const float* Wf  = (const float*)d_in[7];
    const float* bff = (const float*)d_in[8];
    const float* Wi  = (const float*)d_in[9];
    const float* bii = (const float*)d_in[10];
    const float* Wo  = (const float*)d_in[11];
    const float* bo  = (const float*)d_in[12];
    float* out = (float*)d_out;

    float *pq, *pk, *pf, *pi, *ph;
    cudaGetSymbolAddress((void**)&pq, g_q);
    cudaGetSymbolAddress((void**)&pk, g_k);
    cudaGetSymbolAddress((void**)&pf, g_f);
    cudaGetSymbolAddress((void**)&pi, g_i);
    cudaGetSymbolAddress((void**)&ph, g_h);

    gemm4_kernel<<<dim3(2, 64, 4), 256>>>(x, Wq, bq, Wk, bkk, Wf, bff, Wi, bii,
                                          pq, pk, pf, pi);

    nscan_kernel<<<64, 32>>>();
    p1_kernel<<<BB * CH, 256>>>();      // also computes inv_den (needs nscan)
    p2_kernel<<<BB * 32, 256>>>();      // column-split: 256 CTAs
    p3_kernel<<<BB * CH * 8, 128>>>();

    gemm_out_kernel<<<dim3(2, 64), 256>>>(ph, Wo, bo, out);
}

// round 15
// speedup vs baseline: 1.1199x; 1.1199x over previous
#include <cuda_runtime.h>
#include <cuda_fp16.h>
#include <mma.h>
#include <math.h>
#include <stdint.h>

using namespace nvcuda;

// Problem dims
constexpr int BB = 8;
constexpr int SS = 1024;
constexpr int DD = 256;
constexpr int MTOT = BB * SS;          // 8192
constexpr int TC = 16;                 // chunk length
constexpr int CH = SS / TC;            // 64 chunks
constexpr int LDR = 260;               // padded fp32 smem row stride (256 cols)
constexpr int LDRH = 132;              // padded fp32 smem row stride (128 cols)

// Scratch (device globals — no cudaMalloc allowed)
__device__ float g_q[MTOT * DD];
__device__ float g_k[MTOT * DD];
__device__ float g_f[MTOT * DD];
__device__ float g_i[MTOT * DD];
__device__ float g_n[MTOT * DD];
__device__ float g_inv[MTOT + 64];
// split-fp16 tensors for tensor-core GEMMs
__device__ __half g_x16h[MTOT * DD];
__device__ __half g_x16l[MTOT * DD];
__device__ __half g_W16h[5 * DD * DD];    // 0=Wq 1=Wk 2=Wf 3=Wi 4=Wo
__device__ __half g_W16l[5 * DD * DD];
__device__ __half g_h16h[MTOT * DD];
__device__ __half g_h16l[MTOT * DD];
// chunkwise scan scratch
__device__ __half g_Csh[(size_t)BB * CH * DD * DD];  // 64 MB fp16 C snapshots
__device__ float g_G[BB * CH * TC * DD];
__device__ float g_a[BB * CH * TC * DD];
__device__ float g_P[BB * CH * TC * TC];

typedef unsigned long long ull;

// ---- f32x2 helpers ----
__device__ __forceinline__ ull pack2(float lo, float hi) {
    ull r; asm("mov.b64 %0, {%1, %2};" : "=l"(r) : "f"(lo), "f"(hi)); return r;
}
__device__ __forceinline__ ull fma2(ull a, ull b, ull c) {
    ull d; asm("fma.rn.f32x2 %0, %1, %2, %3;" : "=l"(d) : "l"(a), "l"(b), "l"(c)); return d;
}
__device__ __forceinline__ ull mul2(ull a, ull b) {
    ull d; asm("mul.rn.f32x2 %0, %1, %2;" : "=l"(d) : "l"(a), "l"(b)); return d;
}
__device__ __forceinline__ ull add2(ull a, ull b) {
    ull d; asm("add.rn.f32x2 %0, %1, %2;" : "=l"(d) : "l"(a), "l"(b)); return d;
}
__device__ __forceinline__ void unpack2(ull v, float& lo, float& hi) {
    asm("mov.b64 {%0, %1}, %2;" : "=f"(lo), "=f"(hi) : "l"(v));
}
__device__ __forceinline__ float hsum2(ull v) {
    float lo, hi; unpack2(v, lo, hi); return lo + hi;
}
__device__ __forceinline__ uint32_t f2_to_h2(float lo, float hi) {
    __half2 h = __floats2half2_rn(lo, hi);
    return *(uint32_t*)&h;
}

// split one float into hi/lo fp16 pair
__device__ __forceinline__ void split16(float v, __half& hi, __half& lo) {
    hi = __float2half_rn(v);
    lo = __float2half_rn(v - __half2float(hi));
}

// ---- cp.async helpers ----
__device__ __forceinline__ void cp_async16(uint32_t saddr, const void* gptr) {
    asm volatile("cp.async.ca.shared.global [%0], [%1], 16;" :: "r"(saddr), "l"(gptr));
}
__device__ __forceinline__ void cp_commit() { asm volatile("cp.async.commit_group;"); }
template <int N>
__device__ __forceinline__ void cp_wait() {
    asm volatile("cp.async.wait_group %0;" :: "n"(N));
}

// ---------------------------------------------------------------------------
// fp32 -> split-fp16 conversion kernels
// ---------------------------------------------------------------------------
__global__ void conv_x_kernel(const float* __restrict__ x)
{
    const int idx = blockIdx.x * 256 + threadIdx.x;     // float4 index
    float4 v = *(const float4*)(x + (size_t)idx * 4);
    __half h0, l0, h1, l1, h2, l2, h3, l3;
    split16(v.x, h0, l0); split16(v.y, h1, l1);
    split16(v.z, h2, l2); split16(v.w, h3, l3);
    __half hh[4] = {h0, h1, h2, h3};
    __half ll[4] = {l0, l1, l2, l3};
    *(uint2*)(g_x16h + (size_t)idx * 4) = *(uint2*)hh;
    *(uint2*)(g_x16l + (size_t)idx * 4) = *(uint2*)ll;
}

__global__ void conv_w_kernel(
    const float* __restrict__ W0, const float* __restrict__ W1,
    const float* __restrict__ W2, const float* __restrict__ W3,
    const float* __restrict__ W4)
{
    const int z = blockIdx.y;
    const float* W = (z == 0) ? W0 : (z == 1) ? W1 : (z == 2) ? W2
                     : (z == 3) ? W3 : W4;
    const int idx = blockIdx.x * 256 + threadIdx.x;     // float4 index < 16384
    float4 v = *(const float4*)(W + (size_t)idx * 4);
    __half h0, l0, h1, l1, h2, l2, h3, l3;
    split16(v.x, h0, l0); split16(v.y, h1, l1);
    split16(v.z, h2, l2); split16(v.w, h3, l3);
    __half hh[4] = {h0, h1, h2, h3};
    __half ll[4] = {l0, l1, l2, l3};
    *(uint2*)(g_W16h + (size_t)z * DD * DD + (size_t)idx * 4) = *(uint2*)hh;
    *(uint2*)(g_W16l + (size_t)z * DD * DD + (size_t)idx * 4) = *(uint2*)ll;
}

// ---------------------------------------------------------------------------
// Split-fp16 tensor-core GEMM:
//   out = act( Ahi@Bhi^T + Ahi@Blo^T + Alo@Bhi^T + bias )   (fp32 accumulate)
// CTA = 128x128 tile, 256 thr (8 warps as 2x4 of 64x32). K chunks of 64.
// Dynamic smem: 4 fp16 tiles [128][SA] = 72 KB; epilogue reuses as fp32.
// ACT: 0 none, 1 sigmoid, 2 exp. grid (2, 64).
// ---------------------------------------------------------------------------
constexpr int SA = 72;      // fp16 smem stride (halves)
constexpr int SE = 68;      // fp32 epilogue stride (floats)
constexpr int TC_SMEM = 4 * 128 * SA * 2;   // 73728 B

template <int ACT>
__global__ void __launch_bounds__(256) gemm_tc3_kernel(
    const __half* __restrict__ Ah, const __half* __restrict__ Al,
    const __half* __restrict__ Bh, const __half* __restrict__ Bl,
    const float* __restrict__ bias, float* __restrict__ out)
{
    extern __shared__ __align__(16) char smem_u[];
    __half* Ahs = (__half*)smem_u;                // [128][SA]
    __half* Als = Ahs + 128 * SA;
    __half* Bhs = Als + 128 * SA;
    __half* Bls = Bhs + 128 * SA;
    float* ep = (float*)smem_u;                   // epilogue reuse [128][SE]

    const int tid = threadIdx.x;
    const int m0 = blockIdx.y * 128;
    const int n0 = blockIdx.x * 128;
    const int warp = tid >> 5;
    const int warpM = warp & 1;                   // 64-row block
    const int warpN = warp >> 1;                  // 32-col block

    wmma::fragment<wmma::accumulator, 16, 16, 16, float> acc[4][2];
#pragma unroll
    for (int mi = 0; mi < 4; mi++)
#pragma unroll
        for (int ni = 0; ni < 2; ni++)
            wmma::fill_fragment(acc[mi][ni], 0.0f);

    for (int k0 = 0; k0 < DD; k0 += 64) {
        __syncthreads();
        // stage 4 tiles: 128 rows x 8 uint4-segs each
#pragma unroll
        for (int v = 0; v < 4; v++) {
            int idx = tid + v * 256;
            int row = idx >> 3, seg = idx & 7;
            size_t goff = (size_t)(m0 + row) * DD + k0 + seg * 8;
            size_t gofb = (size_t)(n0 + row) * DD + k0 + seg * 8;
            *(uint4*)(Ahs + row * SA + seg * 8) = *(const uint4*)(Ah + goff);
            *(uint4*)(Als + row * SA + seg * 8) = *(const uint4*)(Al + goff);
            *(uint4*)(Bhs + row * SA + seg * 8) = *(const uint4*)(Bh + gofb);
            *(uint4*)(Bls + row * SA + seg * 8) = *(const uint4*)(Bl + gofb);
        }
        __syncthreads();
#pragma unroll
        for (int kk = 0; kk < 64; kk += 16) {
            wmma::fragment<wmma::matrix_a, 16, 16, 16, __half, wmma::row_major> afh[4];
            wmma::fragment<wmma::matrix_b, 16, 16, 16, __half, wmma::col_major> bfh[2];
#pragma unroll
            for (int mi = 0; mi < 4; mi++)
                wmma::load_matrix_sync(afh[mi],
                    Ahs + (warpM * 64 + mi * 16) * SA + kk, SA);
#pragma unroll
            for (int ni = 0; ni < 2; ni++)
                wmma::load_matrix_sync(bfh[ni],
                    Bhs + (warpN * 32 + ni * 16) * SA + kk, SA);
            // hi*hi
#pragma unroll
            for (int mi = 0; mi < 4; mi++)
#pragma unroll
                for (int ni = 0; ni < 2; ni++)
                    wmma::mma_sync(acc[mi][ni], afh[mi], bfh[ni], acc[mi][ni]);
            // lo*hi (reuse bfh)
            {
                wmma::fragment<wmma::matrix_a, 16, 16, 16, __half, wmma::row_major> afl;
#pragma unroll
                for (int mi = 0; mi < 4; mi++) {
                    wmma::load_matrix_sync(afl,
                        Als + (warpM * 64 + mi * 16) * SA + kk, SA);
#pragma unroll
                    for (int ni = 0; ni < 2; ni++)
                        wmma::mma_sync(acc[mi][ni], afl, bfh[ni], acc[mi][ni]);
                }
            }
            // hi*lo (reuse afh)
            {
                wmma::fragment<wmma::matrix_b, 16, 16, 16, __half, wmma::col_major> bfl;
#pragma unroll
                for (int ni = 0; ni < 2; ni++) {
                    wmma::load_matrix_sync(bfl,
                        Bls + (warpN * 32 + ni * 16) * SA + kk, SA);
#pragma unroll
                    for (int mi = 0; mi < 4; mi++)
                        wmma::mma_sync(acc[mi][ni], afh[mi], bfl, acc[mi][ni]);
                }
            }
        }
    }

    // epilogue in 2 column-halves (smem reused as fp32 [128][SE])
#pragma unroll
    for (int h = 0; h < 2; h++) {
        __syncthreads();
        if ((warpN >> 1) == h) {
#pragma unroll
            for (int mi = 0; mi < 4; mi++)
#pragma unroll
                for (int ni = 0; ni < 2; ni++)
                    wmma::store_matrix_sync(
                        ep + (warpM * 64 + mi * 16) * SE
                           + (warpN & 1) * 32 + ni * 16,
                        acc[mi][ni], SE, wmma::mem_row_major);
        }
        __syncthreads();
#pragma unroll
        for (int v = 0; v < 8; v++) {
            int idx = tid + v * 256;
            int row = idx >> 4, segf = idx & 15;
            float4 r = *(const float4*)(ep + row * SE + segf * 4);
            float4 b4 = *(const float4*)(bias + n0 + h * 64 + segf * 4);
            float* rp = &r.x;
            const float* bp = &b4.x;
            float4 o;
            float* op = &o.x;
#pragma unroll
            for (int j = 0; j < 4; j++) {
                float val = rp[j] + bp[j];
                if (ACT == 1) val = 1.0f / (1.0f + expf(-val));
                else if (ACT == 2) val = expf(val);
                op[j] = val;
            }
            *(float4*)(out + (size_t)(m0 + row) * DD + n0 + h * 64 + segf * 4) = o;
        }
    }
}

// ---------------------------------------------------------------------------
// n-scan
// ---------------------------------------------------------------------------
__global__ void nscan_kernel()
{
    const int cid = blockIdx.x * 32 + threadIdx.x;
    const int b = cid >> 8;
    const int j = cid & 255;
    const size_t base = (size_t)b * SS * DD + j;
    float n = 0.0f;
#pragma unroll 16
    for (int t = 0; t < SS; t++) {
        size_t o = base + (size_t)t * DD;
        n = fmaf(g_f[o], n, g_i[o] * g_k[o]);
        g_n[o] = n;
    }
}

// ---------------------------------------------------------------------------
// P1: per (b,chunk) — gates G/a, P = k.q^T, AND inv_den. grid = 512.
// ---------------------------------------------------------------------------
__global__ void __launch_bounds__(256) p1_kernel()
{
    __shared__ float sk[TC][LDR];
    __shared__ float sq[TC][DD];
    __shared__ float sn[TC][DD];

    const int bm = blockIdx.x;
    const int b = bm >> 6, m = bm & 63;
    const int tid = threadIdx.x;
    const size_t mb = (size_t)b * SS * DD;
    const int tt = m * TC;

#pragma unroll
    for (int v = 0; v < 4; v++) {
        int idx = tid + v * 256;
        int t = idx >> 6, gr = idx & 63;
        *(float4*)&sk[t][gr * 4] =
            *(const float4*)(g_k + mb + (size_t)(tt + t) * DD + gr * 4);
        *(float4*)&sq[t][gr * 4] =
            *(const float4*)(g_q + mb + (size_t)(tt + t) * DD + gr * 4);
        *(float4*)&sn[t][gr * 4] =
            *(const float4*)(g_n + mb + (size_t)(tt + t) * DD + gr * 4);
    }
    {
        const int i = tid;
        float g = 1.0f;
#pragma unroll
        for (int u = 0; u < TC; u++) {
            size_t o = mb + (size_t)(tt + u) * DD + i;
            float f = g_f[o], ii = g_i[o], vv = g_q[o];   // v == q
            g *= f;
            float av = __fdividef(ii * vv, g);
            g_G[(size_t)(bm * TC + u) * DD + i] = g;
            g_a[(size_t)(bm * TC + u) * DD + i] = av;
        }
    }
    __syncthreads();

    {
        const int t = tid >> 4, j = tid & 15;
        ull acc0 = 0, acc1 = 0;
#pragma unroll 8
        for (int c = 0; c < DD; c += 4) {
            float4 k4 = *(const float4*)&sk[j][c];
            float4 q4 = *(const float4*)&sq[t][c];
            acc0 = fma2(pack2(k4.x, k4.y), pack2(q4.x, q4.y), acc0);
            acc1 = fma2(pack2(k4.z, k4.w), pack2(q4.z, q4.w), acc1);
        }
        g_P[(size_t)bm * TC * TC + t * TC + j] = hsum2(add2(acc0, acc1));
    }
    if (tid < TC) {
        const int t = tid;
        ull a0 = 0, a1 = 0;
#pragma unroll 8
        for (int c = 0; c < DD; c += 4) {
            float4 n4 = *(const float4*)&sn[t][c];
            float4 q4 = *(const float4*)&sq[t][c];
            a0 = fma2(pack2(n4.x, n4.y), pack2(q4.x, q4.y), a0);
            a1 = fma2(pack2(n4.z, n4.w), pack2(q4.z, q4.w), a1);
        }
        float d = hsum2(add2(a0, a1));
        g_inv[b * SS + tt + t] = 1.0f / fmaxf(fabsf(d), 1.0f);
    }
}

// ---------------------------------------------------------------------------
// P2: serial chunk scan, C in registers, fp16 snapshots. Column-split with
// 4x4 thread tiles: 256 CTAs (b, rg, col half) x 128 threads.
// ---------------------------------------------------------------------------
__global__ void __launch_bounds__(128) p2_kernel()
{
    __shared__ float sk[2][TC][LDRH];
    __shared__ float sa[2][TC][16];
    __shared__ float sg15[2][16];

    const int ch = blockIdx.x & 1;
    const int rg = (blockIdx.x >> 1) & 15;
    const int b  = blockIdx.x >> 5;
    const int rowb = rg * 16;
    const int colb = ch * 128;
    const int tid = threadIdx.x;
    const int rq = tid >> 5;              // rows 4rq..4rq+3
    const int cq = tid & 31;              // cols 4cq..4cq+3 (within half)
    const size_t mb = (size_t)b * SS * DD;

    const uint32_t sk_u = (uint32_t)__cvta_generic_to_shared(&sk[0][0][0]);
    const uint32_t sa_u = (uint32_t)__cvta_generic_to_shared(&sa[0][0][0]);
    const uint32_t sg_u = (uint32_t)__cvta_generic_to_shared(&sg15[0][0]);

    auto fill = [&](int st, int mm) {
        const int tt = mm * TC;
        const int bm = b * CH + mm;
#pragma unroll
        for (int v = 0; v < 4; v++) {
            int idx = tid + v * 128;
            int t = idx >> 5, gr = idx & 31;
            cp_async16(sk_u + (uint32_t)(((st * TC + t) * LDRH + gr * 4) * 4),
                       g_k + mb + (size_t)(tt + t) * DD + colb + gr * 4);
        }
        if (tid < 64) {
            int s = tid >> 2, p = tid & 3;
            cp_async16(sa_u + (uint32_t)(((st * TC + s) * 16 + p * 4) * 4),
                       g_a + (size_t)(bm * TC + s) * DD + rowb + p * 4);
        } else if (tid < 68) {
            int p = tid - 64;
            cp_async16(sg_u + (uint32_t)((st * 16 + p * 4) * 4),
                       g_G + (size_t)(bm * TC + 15) * DD + rowb + p * 4);
        }
    };

    ull Cp[4][2];
#pragma unroll
    for (int r = 0; r < 4; r++) { Cp[r][0] = 0ull; Cp[r][1] = 0ull; }

    fill(0, 0); cp_commit();
    fill(1, 1); cp_commit();

    for (int m = 0; m < CH; m++) {
        const int st = m & 1;
        cp_wait<1>();
        __syncthreads();

        // snapshot C (fp16)
        {
            const int bm = b * CH + m;
#pragma unroll
            for (int r = 0; r < 4; r++) {
                float l0, h0, l1, h1;
                unpack2(Cp[r][0], l0, h0);
                unpack2(Cp[r][1], l1, h1);
                uint2 u;
                u.x = f2_to_h2(l0, h0);
                u.y = f2_to_h2(l1, h1);
                __half* dst = g_Csh + ((size_t)bm * DD + rowb + rq * 4 + r) * DD
                              + colb + cq * 4;
                *(uint2*)dst = u;
            }
        }

        // update
        {
            ull acc[4][2];
#pragma unroll
            for (int r = 0; r < 4; r++) { acc[r][0] = 0ull; acc[r][1] = 0ull; }
#pragma unroll 4
            for (int s = 0; s < TC; s++) {
                float4 a4 = *(const float4*)&sa[st][s][rq * 4];
                float4 k4 = *(const float4*)&sk[st][s][cq * 4];
                ull kxy = pack2(k4.x, k4.y), kzw = pack2(k4.z, k4.w);
                ull a0 = pack2(a4.x, a4.x);
                ull a1 = pack2(a4.y, a4.y);
                ull a2 = pack2(a4.z, a4.z);
                ull a3 = pack2(a4.w, a4.w);
                acc[0][0] = fma2(a0, kxy, acc[0][0]); acc[0][1] = fma2(a0, kzw, acc[0][1]);
                acc[1][0] = fma2(a1, kxy, acc[1][0]); acc[1][1] = fma2(a1, kzw, acc[1][1]);
                acc[2][0] = fma2(a2, kxy, acc[2][0]); acc[2][1] = fma2(a2, kzw, acc[2][1]);
                acc[3][0] = fma2(a3, kxy, acc[3][0]); acc[3][1] = fma2(a3, kzw, acc[3][1]);
            }
            float4 g4 = *(const float4*)&sg15[st][rq * 4];
            float gv[4] = {g4.x, g4.y, g4.z, g4.w};
#pragma unroll
            for (int r = 0; r < 4; r++) {
                ull g2 = pack2(gv[r], gv[r]);
                Cp[r][0] = mul2(g2, add2(Cp[r][0], acc[r][0]));
                Cp[r][1] = mul2(g2, add2(Cp[r][1], acc[r][1]));
            }
        }
        __syncthreads();

        if (m + 2 < CH) fill(st, m + 2);
        cp_commit();
    }
}

// ---------------------------------------------------------------------------
// P3: per (b,chunk,32-row group) — CQ = Cs.q^T + triangular combine.
// Writes split-fp16 h for the output GEMM. grid = 4096, 128 threads.
// ---------------------------------------------------------------------------
struct P3Smem {
    float q[TC][LDR];
    float Cs[32][LDR];
    float a[TC][32];
    float G[TC][32];
    float P[TC][TC];
    float inv[TC];
    float htile[TC][32];
};

__global__ void __launch_bounds__(128) p3_kernel()
{
    __shared__ P3Smem S;
    const int blk = blockIdx.x;
    const int bm = blk >> 3;
    const int rg = blk & 7;
    const int b = bm >> 6, m = bm & 63;
    const int tid = threadIdx.x;
    const int rowb = rg * 32;
    const size_t mb = (size_t)b * SS * DD;
    const int tt = m * TC;

#pragma unroll
    for (int v = 0; v < 8; v++) {
        int idx = tid + v * 128;
        int t = idx >> 6, gr = idx & 63;
        *(float4*)&S.q[t][gr * 4] =
            *(const float4*)(g_q + mb + (size_t)(tt + t) * DD + gr * 4);
    }
#pragma unroll
    for (int v = 0; v < 8; v++) {
        int idx = tid + v * 128;
        int r = idx >> 5, u = idx & 31;
        uint4 raw = *(const uint4*)(g_Csh + ((size_t)bm * DD + rowb + r) * DD + u * 8);
        const __half2* hp = (const __half2*)&raw;
        float2 f0 = __half22float2(hp[0]);
        float2 f1 = __half22float2(hp[1]);
        float2 f2 = __half22float2(hp[2]);
        float2 f3 = __half22float2(hp[3]);
        *(float4*)&S.Cs[r][u * 8]     = make_float4(f0.x, f0.y, f1.x, f1.y);
        *(float4*)&S.Cs[r][u * 8 + 4] = make_float4(f2.x, f2.y, f3.x, f3.y);
    }
#pragma unroll
    for (int v = 0; v < 4; v++) {
        int idx = tid + v * 128;
        int s = (idx & 127) >> 3, p = idx & 7;
        if (idx < 128)
            *(float4*)&S.a[s][p * 4] =
                *(const float4*)(g_a + (size_t)(bm * TC + s) * DD + rowb + p * 4);
        else if (idx < 256)
            *(float4*)&S.G[s][p * 4] =
                *(const float4*)(g_G + (size_t)(bm * TC + s) * DD + rowb + p * 4);
        else if (idx < 320) {
            int ii = idx - 256;
            int t2 = ii >> 2, p2 = ii & 3;
            *(float4*)&S.P[t2][p2 * 4] =
                *(const float4*)(g_P + (size_t)bm * 256 + t2 * 16 + p2 * 4);
        } else if (idx < 324) {
            int p3 = idx - 320;
            *(float4*)&S.inv[p3 * 4] =
                *(const float4*)(g_inv + b * SS + tt + p3 * 4);
        }
    }
    __syncthreads();

    const int r2 = tid & 15;
    const int nh = tid >> 4;
    const int rA = r2, rB = r2 + 16;
    const int tA = nh, tB = nh + 8;

    ull cAA0 = 0, cAA1 = 0, cAB0 = 0, cAB1 = 0;
    ull cBA0 = 0, cBA1 = 0, cBB0 = 0, cBB1 = 0;
    const float* CrA = &S.Cs[rA][0];
    const float* CrB = &S.Cs[rB][0];
    const float* q0 = &S.q[tA][0];
    const float* q1 = &S.q[tB][0];
#pragma unroll 8
    for (int c = 0; c < DD; c += 4) {
        float4 CA = *(const float4*)(CrA + c);
        float4 CB = *(const float4*)(CrB + c);
        float4 B0 = *(const float4*)(q0 + c);
        float4 B1 = *(const float4*)(q1 + c);
        ull Axy = pack2(CA.x, CA.y), Azw = pack2(CA.z, CA.w);
        ull Bxy = pack2(CB.x, CB.y), Bzw = pack2(CB.z, CB.w);
        ull q0xy = pack2(B0.x, B0.y), q0zw = pack2(B0.z, B0.w);
        ull q1xy = pack2(B1.x, B1.y), q1zw = pack2(B1.z, B1.w);
        cAA0 = fma2(Axy, q0xy, cAA0); cAA1 = fma2(Azw, q0zw, cAA1);
        cAB0 = fma2(Axy, q1xy, cAB0); cAB1 = fma2(Azw, q1zw, cAB1);
        cBA0 = fma2(Bxy, q0xy, cBA0); cBA1 = fma2(Bzw, q0zw, cBA1);
        cBB0 = fma2(Bxy, q1xy, cBB0); cBB1 = fma2(Bzw, q1zw, cBB1);
    }
    float CQ_AA = hsum2(add2(cAA0, cAA1));
    float CQ_AB = hsum2(add2(cAB0, cAB1));
    float CQ_BA = hsum2(add2(cBA0, cBA1));
    float CQ_BB = hsum2(add2(cBB0, cBB1));

    {
        float nAA = CQ_AA, nBA = CQ_BA;
#pragma unroll
        for (int s = 0; s < TC; s++)
            if (s <= tA) {
                float p = S.P[tA][s];
                nAA = fmaf(S.a[s][rA], p, nAA);
                nBA = fmaf(S.a[s][rB], p, nBA);
            }
        S.htile[tA][rA] = S.G[tA][rA] * nAA * S.inv[tA];
        S.htile[tA][rB] = S.G[tA][rB] * nBA * S.inv[tA];

        float nAB = CQ_AB, nBB = CQ_BB;
#pragma unroll
        for (int s = 0; s < TC; s++)
            if (s <= tB) {
                float p = S.P[tB][s];
                nAB = fmaf(S.a[s][rA], p, nAB);
                nBB = fmaf(S.a[s][rB], p, nBB);
            }
        S.htile[tB][rA] = S.G[tB][rA] * nAB * S.inv[tB];
        S.htile[tB][rB] = S.G[tB][rB] * nBB * S.inv[tB];
    }
    __syncthreads();

    // split-fp16 h write: thread -> 4 values
    {
        const int t = tid >> 3, seg = tid & 7;
        float4 r = *(const float4*)&S.htile[t][seg * 4];
        __half h0, l0, h1, l1, h2, l2, h3, l3;
        split16(r.x, h0, l0); split16(r.y, h1, l1);
        split16(r.z, h2, l2); split16(r.w, h3, l3);
        __half hh[4] = {h0, h1, h2, h3};
        __half ll[4] = {l0, l1, l2, l3};
        size_t off = mb + (size_t)(tt + t) * DD + rowb + seg * 4;
        *(uint2*)(g_h16h + off) = *(uint2*)hh;
        *(uint2*)(g_h16l + off) = *(uint2*)ll;
    }
}

// ---------------------------------------------------------------------------
// Launch
// ---------------------------------------------------------------------------
extern "C" void kernel_launch(void* const* d_in, const int* in_sizes, int n_in,
                              void* d_out, int out_size)
{
    const float* x   = (const float*)d_in[0];
    const float* Wq  = (const float*)d_in[1];
    const float* bq  = (const float*)d_in[2];
    const float* Wk  = (const float*)d_in[3];
    const float* bkk = (const float*)d_in[4];
    // d_in[5] = Wv, d_in[6] = bv — unused (reference uses W_q for v)
    const float* Wf  = (const float*)d_in[7];
    const float* bff = (const float*)d_in[8];
    const float* Wi  = (const float*)d_in[9];
    const float* bii = (const float*)d_in[10];
    const float* Wo  = (const float*)d_in[11];
    const float* bo  = (const float*)d_in[12];
    float* out = (float*)d_out;

    float *pq, *pk, *pf, *pi;
    __half *pxh, *pxl, *pwh, *pwl, *phh, *phl;
    cudaGetSymbolAddress((void**)&pq, g_q);
    cudaGetSymbolAddress((void**)&pk, g_k);
    cudaGetSymbolAddress((void**)&pf, g_f);
    cudaGetSymbolAddress((void**)&pi, g_i);
    cudaGetSymbolAddress((void**)&pxh, g_x16h);
    cudaGetSymbolAddress((void**)&pxl, g_x16l);
    cudaGetSymbolAddress((void**)&pwh, g_W16h);
    cudaGetSymbolAddress((void**)&pwl, g_W16l);
    cudaGetSymbolAddress((void**)&phh, g_h16h);
    cudaGetSymbolAddress((void**)&phl, g_h16l);

    static int attr_set = 0;
    if (!attr_set) {
        cudaFuncSetAttribute(gemm_tc3_kernel<0>,
                             cudaFuncAttributeMaxDynamicSharedMemorySize, TC_SMEM);
        cudaFuncSetAttribute(gemm_tc3_kernel<1>,
                             cudaFuncAttributeMaxDynamicSharedMemorySize, TC_SMEM);
        cudaFuncSetAttribute(gemm_tc3_kernel<2>,
                             cudaFuncAttributeMaxDynamicSharedMemorySize, TC_SMEM);
        attr_set = 1;
    }

    // split-fp16 conversions
    conv_x_kernel<<<MTOT * DD / 4 / 256, 256>>>(x);
    conv_w_kernel<<<dim3(DD * DD / 4 / 256, 5), 256>>>(Wq, Wk, Wf, Wi, Wo);

    // projections (split-fp16 tensor cores)
    dim3 ggrid(2, 64);
    gemm_tc3_kernel<0><<<ggrid, 256, TC_SMEM>>>(pxh, pxl,
        pwh + 0 * DD * DD, pwl + 0 * DD * DD, bq,  pq);
    gemm_tc3_kernel<0><<<ggrid, 256, TC_SMEM>>>(pxh, pxl,
        pwh + 1 * DD * DD, pwl + 1 * DD * DD, bkk, pk);
    gemm_tc3_kernel<1><<<ggrid, 256, TC_SMEM>>>(pxh, pxl,
        pwh + 2 * DD * DD, pwl + 2 * DD * DD, bff, pf);
    gemm_tc3_kernel<2><<<ggrid, 256, TC_SMEM>>>(pxh, pxl,
        pwh + 3 * DD * DD, pwl + 3 * DD * DD, bii, pi);

    nscan_kernel<<<64, 32>>>();
    p1_kernel<<<BB * CH, 256>>>();
    p2_kernel<<<BB * 32, 128>>>();
    p3_kernel<<<BB * CH * 8, 128>>>();

    // output projection
    gemm_tc3_kernel<0><<<ggrid, 256, TC_SMEM>>>(phh, phl,
        pwh + 4 * DD * DD, pwl + 4 * DD * DD, bo, out);
}